// round 11
// baseline (speedup 1.0000x reference)
#include <cuda_runtime.h>
#include <cuda_bf16.h>
#include <cuda_pipeline.h>

// Problem constants
#define B_ 4
#define F_ 16
#define N_ 1024
#define V_ 4

#define TPB 256
#define NB_REC 16
#define NB_IDENT 256   // V*B*F groups
#define NB_TOTAL 888   // 148 SMs * 6 blocks, one wave

// corr: [V,V,B,N,N] = 64 matrices of 1024x1024 fp32
#define TOT_F4 16777216      // 64 * 1024*1024 / 4
#define N_ROWS 65536         // 64 * 1024 band rows
#define BAND_RPB 74          // ceil(N_ROWS / NB_TOTAL)
#define STAGES 8             // cp.async ring depth (7 outstanding)

#define LN2 0.6931471805599453f

// -------- scratch (device globals) --------
__device__ float  g_att_partial[NB_TOTAL];
__device__ float  g_rec_partial[NB_REC][8];   // sum, cnt, mn0..2, mx0..2
__device__ double g_ident_partial[NB_IDENT];
__device__ unsigned int g_done;               // last-block counter (self-resetting)

// -------- reductions --------
__device__ __forceinline__ float warpSum(float v) {
#pragma unroll
    for (int o = 16; o; o >>= 1) v += __shfl_xor_sync(0xffffffffu, v, o);
    return v;
}
__device__ __forceinline__ float warpMin(float v) {
#pragma unroll
    for (int o = 16; o; o >>= 1) v = fminf(v, __shfl_xor_sync(0xffffffffu, v, o));
    return v;
}
__device__ __forceinline__ float warpMax(float v) {
#pragma unroll
    for (int o = 16; o; o >>= 1) v = fmaxf(v, __shfl_xor_sync(0xffffffffu, v, o));
    return v;
}
__device__ __forceinline__ double warpSumD(double v) {
#pragma unroll
    for (int o = 16; o; o >>= 1) v += __shfl_xor_sync(0xffffffffu, v, o);
    return v;
}

__device__ float blockSum(float v, float* sh) {
    int lane = threadIdx.x & 31, w = threadIdx.x >> 5;
    v = warpSum(v);
    if (lane == 0) sh[w] = v;
    __syncthreads();
    float r = (threadIdx.x < (TPB >> 5)) ? sh[threadIdx.x] : 0.0f;
    if (w == 0) r = warpSum(r);
    __syncthreads();
    return r;
}
__device__ double blockSumD(double v, double* sh) {
    int lane = threadIdx.x & 31, w = threadIdx.x >> 5;
    v = warpSumD(v);
    if (lane == 0) sh[w] = v;
    __syncthreads();
    double r = (threadIdx.x < (TPB >> 5)) ? sh[threadIdx.x] : 0.0;
    if (w == 0) r = warpSumD(r);
    __syncthreads();
    return r;
}
__device__ float blockMin(float v, float* sh) {
    int lane = threadIdx.x & 31, w = threadIdx.x >> 5;
    v = warpMin(v);
    if (lane == 0) sh[w] = v;
    __syncthreads();
    float r = (threadIdx.x < (TPB >> 5)) ? sh[threadIdx.x] : 1e30f;
    if (w == 0) r = warpMin(r);
    __syncthreads();
    return r;
}
__device__ float blockMax(float v, float* sh) {
    int lane = threadIdx.x & 31, w = threadIdx.x >> 5;
    v = warpMax(v);
    if (lane == 0) sh[w] = v;
    __syncthreads();
    float r = (threadIdx.x < (TPB >> 5)) ? sh[threadIdx.x] : -1e30f;
    if (w == 0) r = warpMax(r);
    __syncthreads();
    return r;
}

// per-float4 BCE piece: accm += sum max(x,0); p *= (1+exp(-|x|)) per element
__device__ __forceinline__ void bce4(const float4 v, float& accm, float& accl2) {
    float p = 1.0f;
    float e0 = __expf(-fabsf(v.x));
    float e1 = __expf(-fabsf(v.y));
    float e2 = __expf(-fabsf(v.z));
    float e3 = __expf(-fabsf(v.w));
    accm += fmaxf(v.x, 0.0f) + fmaxf(v.y, 0.0f);
    accm += fmaxf(v.z, 0.0f) + fmaxf(v.w, 0.0f);
    p = __fmaf_rn(p, e0, p);
    p = __fmaf_rn(p, e1, p);
    p = __fmaf_rn(p, e2, p);
    p = __fmaf_rn(p, e3, p);
    accl2 += __log2f(p);
}

// ===========================================================================
__global__ void __launch_bounds__(TPB, 6) fused_kernel(
    const float* __restrict__ refined,   // [B,F,N,3]
    const float* __restrict__ gt,        // [B,F,N,3]
    const int*   __restrict__ visp,      // [B,F,N]
    const float* __restrict__ proj,      // [V,B,3,4]
    const float* __restrict__ tracks,    // [V,B,F,N,2]
    const float* __restrict__ corr,      // [V,V,B,N,N]
    float* __restrict__ out, int out_size)
{
    const int tid = threadIdx.x;
    const int bid = blockIdx.x;
    __shared__ float4 ring[STAGES * TPB];        // 32 KB cp.async ring
    __shared__ float sred[8];
    __shared__ double sredd[8];
    __shared__ bool s_last;
    __shared__ unsigned int visbits[B_][32];     // frame-0 visibility bitmask

    if (tid < B_ * 32) {
        int b = tid >> 5, wi = tid & 31;
        const int* vp = visp + b * (F_ * N_) + wi * 32;  // frame 0
        unsigned int bits = 0;
#pragma unroll
        for (int k = 0; k < 32; k++) bits |= (vp[k] > 0 ? 1u : 0u) << k;
        visbits[b][wi] = bits;
    }
    __syncthreads();

    // ---------------- small per-block jobs first ----------------
    if (bid < NB_REC) {
        // reconstruction loss partials
        const int rb = bid;
        float ssum = 0.0f, scnt = 0.0f;
        float mn0 = 1e30f, mn1 = 1e30f, mn2 = 1e30f;
        float mx0 = -1e30f, mx1 = -1e30f, mx2 = -1e30f;
        const int p0 = rb * 4096;
#pragma unroll 4
        for (int q = 0; q < 16; q++) {
            int p = p0 + tid + q * TPB;
            int vv = visp[p];
            float gx = gt[3 * p + 0], gy = gt[3 * p + 1], gz = gt[3 * p + 2];
            float px = refined[3 * p + 0], py = refined[3 * p + 1], pz = refined[3 * p + 2];
            if (vv > 0) {
                float dx = px - gx, dy = py - gy, dz = pz - gz;
                ssum += dx * dx + dy * dy + dz * dz;
                scnt += 1.0f;
                mn0 = fminf(mn0, gx); mn1 = fminf(mn1, gy); mn2 = fminf(mn2, gz);
                mx0 = fmaxf(mx0, gx); mx1 = fmaxf(mx1, gy); mx2 = fmaxf(mx2, gz);
            }
        }
        float rs = blockSum(ssum, sred);
        float rc = blockSum(scnt, sred);
        float a0 = blockMin(mn0, sred), a1 = blockMin(mn1, sred), a2 = blockMin(mn2, sred);
        float b0 = blockMax(mx0, sred), b1 = blockMax(mx1, sred), b2 = blockMax(mx2, sred);
        if (tid == 0) {
            g_rec_partial[rb][0] = rs; g_rec_partial[rb][1] = rc;
            g_rec_partial[rb][2] = a0; g_rec_partial[rb][3] = a1; g_rec_partial[rb][4] = a2;
            g_rec_partial[rb][5] = b0; g_rec_partial[rb][6] = b1; g_rec_partial[rb][7] = b2;
        }
    } else if (bid < NB_REC + NB_IDENT) {
        // identity loss: one block per (v,b,f) group.
        // Eigen-ordered fp32 FMA chain + IEEE division (bit-matches reference;
        // do not touch — the loss is heavy-tailed in 1/h2).
        const int gid = bid - NB_REC;         // == (v*B + b)*F + f
        const int f = gid & (F_ - 1);
        const int bb = (gid >> 4) & (B_ - 1);
        const int vv = gid >> 6;
        const float2* trk = (const float2*)(tracks + (long long)gid * (N_ * 2));
        __shared__ float P[12];
        __shared__ float s_wh[2];
        if (tid < 12) P[tid] = proj[(vv * B_ + bb) * 12 + tid];

        float tx[4], ty[4];
        float mnx = 1e30f, mny = 1e30f, mxx = -1e30f, mxy = -1e30f;
#pragma unroll
        for (int q = 0; q < 4; q++) {
            int n = tid + q * TPB;
            float2 t2 = trk[n];
            tx[q] = t2.x; ty[q] = t2.y;
            if (fabsf(t2.x) + fabsf(t2.y) > 1e-6f) {
                mnx = fminf(mnx, t2.x); mxx = fmaxf(mxx, t2.x);
                mny = fminf(mny, t2.y); mxy = fmaxf(mxy, t2.y);
            }
        }
        float rmnx = blockMin(mnx, sred), rmxx = blockMax(mxx, sred);
        float rmny = blockMin(mny, sred), rmxy = blockMax(mxy, sred);
        if (tid == 0) {
            bool anyv = (rmnx <= 1e29f) || (rmny <= 1e29f);
            float whx = anyv ? fmaxf(224.0f, __fadd_rn(__fadd_rn(rmxx, -rmnx), 1e-6f)) : 224.0f;
            float why = anyv ? fmaxf(224.0f, __fadd_rn(__fadd_rn(rmxy, -rmny), 1e-6f)) : 224.0f;
            s_wh[0] = whx;
            s_wh[1] = why;
        }
        __syncthreads();
        float whx = s_wh[0], why = s_wh[1];
        const float* pb = refined + ((long long)(bb * F_ + f) * N_) * 3;
        double errs = 0.0;
#pragma unroll
        for (int q = 0; q < 4; q++) {
            int n = tid + q * TPB;
            float X = pb[3 * n + 0], Y = pb[3 * n + 1], Z = pb[3 * n + 2];
            float h0 = __fmaf_rn(P[3], 1.0f, __fmaf_rn(P[2], Z, __fmaf_rn(P[1], Y, __fmul_rn(P[0], X))));
            float h1 = __fmaf_rn(P[7], 1.0f, __fmaf_rn(P[6], Z, __fmaf_rn(P[5], Y, __fmul_rn(P[4], X))));
            float h2 = __fmaf_rn(P[11], 1.0f, __fmaf_rn(P[10], Z, __fmaf_rn(P[9], Y, __fmul_rn(P[8], X))));
            float den = __fadd_rn(h2, 1e-10f);
            float px = __fdiv_rn(h0, den);
            float py = __fdiv_rn(h1, den);
            float ex = __fdiv_rn(__fadd_rn(px, -tx[q]), whx);
            float ey = __fdiv_rn(__fadd_rn(py, -ty[q]), why);
            float e = __fadd_rn(__fmul_rn(ex, ex), __fmul_rn(ey, ey));
            errs += (double)e;
        }
        double tot = blockSumD(errs, sredd);
        if (tid == 0) g_ident_partial[gid] = tot * (1.0 / (double)N_);
    }

    // ---------------- attention BCE: every block participates ----------------
    float acc = 0.0f;

    // ---- band correction: BAND_RPB rows per block ----
    {
        int r0 = bid * BAND_RPB;
        for (int r = tid; r < BAND_RPB; r += TPB) {
            int row = r0 + r;
            if (row < N_ROWS) {
                int m = row >> 10;                   // matrix 0..63
                int i = row & 1023;
                int b = m & (B_ - 1);
                unsigned int vi = (visbits[b][i >> 5] >> (i & 31)) & 1u;
                const float* rowp = corr + ((long long)m << 20) + ((long long)i << 10);
                int jlo = (i >= 2) ? i - 2 : 0;
                int jhi = (i <= 1021) ? i + 2 : 1023;
                float d = 0.0f;
#pragma unroll 5
                for (int j = jlo; j <= jhi; j++) {
                    int ad = (i > j) ? (i - j) : (j - i);
                    unsigned int vj = (visbits[b][j >> 5] >> (j & 31)) & 1u;
                    float band = (ad == 0) ? 1.0f : ((ad == 1) ? 0.7f : 0.49f);
                    float g = (vi | vj) ? band : 0.0f;
                    float x = rowp[j];
                    float mx = fmaxf(x, 0.0f);
                    float l = __logf(1.0f + __expf(-fabsf(x)));
                    d += 2.0f * g * (mx + l) - (1.0f + 2.0f * g) * x * g;
                }
                acc += d;
            }
        }
    }

    // ---- uniform streaming pass: per-thread 8-stage cp.async ring ----
    // Each thread copies 16 B/stage into its OWN smem slot and reads back its
    // own slot after __pipeline_wait_prior — per-thread visibility, no block
    // sync in the hot loop. 7 outstanding LDGSTS x 16 B x 1536 thr/SM = 172 KB
    // in flight per SM: load issue fully decoupled from the compute phase.
    {
        const float4* c4 = (const float4*)corr;
        const long long STR = (long long)NB_TOTAL * TPB;
        const long long idx0 = (long long)bid * TPB + tid;
        const int nIter = (int)((TOT_F4 - 1 - idx0) / STR) + 1;
        float4* slot = ring + tid;                   // stride TPB between stages

        float accm0 = 0.0f, accl0 = 0.0f;
        float accm1 = 0.0f, accl1 = 0.0f;

#pragma unroll
        for (int s = 0; s < STAGES - 1; s++) {
            if (s < nIter)
                __pipeline_memcpy_async(slot + s * TPB, c4 + (idx0 + (long long)s * STR), 16);
            __pipeline_commit();
        }
        for (int i = 0; i < nIter; i++) {
            __pipeline_wait_prior(STAGES - 2);
            float4 v = slot[(i & (STAGES - 1)) * TPB];
            int nxt = i + STAGES - 1;
            if (nxt < nIter)
                __pipeline_memcpy_async(slot + (nxt & (STAGES - 1)) * TPB,
                                        c4 + (idx0 + (long long)nxt * STR), 16);
            __pipeline_commit();
            if (i & 1) bce4(v, accm1, accl1);
            else       bce4(v, accm0, accl0);
        }
        __pipeline_wait_prior(0);
        acc += (accm0 + accm1) + (accl0 + accl1) * LN2;
    }

    float tot = blockSum(acc, sred);
    if (tid == 0) g_att_partial[bid] = tot;

    // ================= last-block finalize (no second launch) =================
    if (tid == 0) {
        __threadfence();
        unsigned int t = atomicAdd(&g_done, 1u);
        s_last = (t == (unsigned int)(NB_TOTAL - 1));
    }
    __syncthreads();
    if (s_last) {
        __threadfence();
        int lane = tid & 31, w = tid >> 5;
        __shared__ double shd[8];

        double a = 0.0;
        for (int i = tid; i < NB_TOTAL; i += TPB) a += (double)g_att_partial[i];
        a = warpSumD(a);
        if (lane == 0) shd[w] = a;
        __syncthreads();
        double asum = (tid < 8) ? shd[tid] : 0.0;
        if (w == 0) asum = warpSumD(asum);
        __syncthreads();

        double id = (tid < NB_IDENT) ? g_ident_partial[tid] : 0.0;
        id = warpSumD(id);
        if (lane == 0) shd[w] = id;
        __syncthreads();
        double idsum = (tid < 8) ? shd[tid] : 0.0;
        if (w == 0) idsum = warpSumD(idsum);

        if (tid == 0) {
            float ssum = 0.0f, scnt = 0.0f;
            float mn[3] = {1e30f, 1e30f, 1e30f};
            float mx[3] = {-1e30f, -1e30f, -1e30f};
            for (int r = 0; r < NB_REC; r++) {
                ssum += g_rec_partial[r][0];
                scnt += g_rec_partial[r][1];
                for (int c = 0; c < 3; c++) {
                    mn[c] = fminf(mn[c], g_rec_partial[r][2 + c]);
                    mx[c] = fmaxf(mx[c], g_rec_partial[r][5 + c]);
                }
            }
            float rng = fmaxf(fmaxf(mx[0] - mn[0], mx[1] - mn[1]), mx[2] - mn[2]);
            float scale = rng + 1e-6f;
            float num = scnt * 3.0f;
            if (!(num > 0.0f)) scale = 1.0f;
            float rec = (ssum / fmaxf(num, 1.0f)) / (scale * scale);

            float ident = (float)(idsum / (double)NB_IDENT);
            float att = (float)(asum / (64.0 * 1048576.0));
            float total = rec + 1.0f * ident + 0.5f * att;
            if (out_size >= 4) {
                out[0] = total; out[1] = rec; out[2] = ident; out[3] = att;
            } else if (out_size >= 1) {
                out[0] = total;
            }
            g_done = 0;   // reset for next (graph-replayed) launch
        }
    }
}

// ===========================================================================
extern "C" void kernel_launch(void* const* d_in, const int* in_sizes, int n_in,
                              void* d_out, int out_size) {
    const float* refined = (const float*)d_in[0];
    const float* gt      = (const float*)d_in[1];
    const int*   visp    = (const int*)  d_in[2];
    const float* proj    = (const float*)d_in[3];
    const float* tracks  = (const float*)d_in[4];
    const float* corr    = (const float*)d_in[5];
    (void)in_sizes; (void)n_in;

    fused_kernel<<<NB_TOTAL, TPB>>>(refined, gt, visp, proj, tracks, corr,
                                    (float*)d_out, out_size);
}

// round 14
// speedup vs baseline: 1.2583x; 1.2583x over previous
#include <cuda_runtime.h>
#include <cuda_bf16.h>

// Problem constants
#define B_ 4
#define F_ 16
#define N_ 1024
#define V_ 4

#define TPB 256
#define NB_REC 16
#define NB_IDENT 256   // V*B*F groups
#define NB_ATT 616
#define NB_TOTAL (NB_REC + NB_IDENT + NB_ATT)   // 888 = 148 SMs * 6 blocks

// corr: [V,V,B,N,N] = 64 matrices of 1024x1024 fp32
#define TOT_F4 16777216   // 64 * 1024*1024 / 4
#define N_ROWS 65536      // 64 * 1024 band rows
#define BAND_RPB 107      // ceil(N_ROWS / NB_ATT) rows per att block

#define LN2 0.6931471805599453f

// -------- scratch (device globals; every slot written every launch) --------
__device__ float  g_att_partial[NB_ATT];
__device__ float  g_rec_partial[NB_REC][8];   // sum, cnt, mn0..2, mx0..2
__device__ double g_ident_partial[NB_IDENT];
__device__ unsigned int g_done;               // last-block counter (self-resetting)

// -------- reductions --------
__device__ __forceinline__ float warpSum(float v) {
#pragma unroll
    for (int o = 16; o; o >>= 1) v += __shfl_xor_sync(0xffffffffu, v, o);
    return v;
}
__device__ __forceinline__ float warpMin(float v) {
#pragma unroll
    for (int o = 16; o; o >>= 1) v = fminf(v, __shfl_xor_sync(0xffffffffu, v, o));
    return v;
}
__device__ __forceinline__ float warpMax(float v) {
#pragma unroll
    for (int o = 16; o; o >>= 1) v = fmaxf(v, __shfl_xor_sync(0xffffffffu, v, o));
    return v;
}
__device__ __forceinline__ double warpSumD(double v) {
#pragma unroll
    for (int o = 16; o; o >>= 1) v += __shfl_xor_sync(0xffffffffu, v, o);
    return v;
}

__device__ float blockSum(float v, float* sh) {
    int lane = threadIdx.x & 31, w = threadIdx.x >> 5;
    v = warpSum(v);
    if (lane == 0) sh[w] = v;
    __syncthreads();
    float r = (threadIdx.x < (TPB >> 5)) ? sh[threadIdx.x] : 0.0f;
    if (w == 0) r = warpSum(r);
    __syncthreads();
    return r;
}
__device__ double blockSumD(double v, double* sh) {
    int lane = threadIdx.x & 31, w = threadIdx.x >> 5;
    v = warpSumD(v);
    if (lane == 0) sh[w] = v;
    __syncthreads();
    double r = (threadIdx.x < (TPB >> 5)) ? sh[threadIdx.x] : 0.0;
    if (w == 0) r = warpSumD(r);
    __syncthreads();
    return r;
}
__device__ float blockMin(float v, float* sh) {
    int lane = threadIdx.x & 31, w = threadIdx.x >> 5;
    v = warpMin(v);
    if (lane == 0) sh[w] = v;
    __syncthreads();
    float r = (threadIdx.x < (TPB >> 5)) ? sh[threadIdx.x] : 1e30f;
    if (w == 0) r = warpMin(r);
    __syncthreads();
    return r;
}
__device__ float blockMax(float v, float* sh) {
    int lane = threadIdx.x & 31, w = threadIdx.x >> 5;
    v = warpMax(v);
    if (lane == 0) sh[w] = v;
    __syncthreads();
    float r = (threadIdx.x < (TPB >> 5)) ? sh[threadIdx.x] : -1e30f;
    if (w == 0) r = warpMax(r);
    __syncthreads();
    return r;
}

__device__ __forceinline__ void prefetchL2(const void* p) {
    asm volatile("prefetch.global.L2 [%0];" :: "l"(p));
}

// per-float4 BCE piece: accm += sum max(x,0); p *= (1+exp(-|x|)) per element
__device__ __forceinline__ void bce4(const float4 v, float& accm, float& accl2) {
    float p = 1.0f;
    float e0 = __expf(-fabsf(v.x));
    float e1 = __expf(-fabsf(v.y));
    float e2 = __expf(-fabsf(v.z));
    float e3 = __expf(-fabsf(v.w));
    accm += fmaxf(v.x, 0.0f) + fmaxf(v.y, 0.0f);
    accm += fmaxf(v.z, 0.0f) + fmaxf(v.w, 0.0f);
    p = __fmaf_rn(p, e0, p);
    p = __fmaf_rn(p, e1, p);
    p = __fmaf_rn(p, e2, p);
    p = __fmaf_rn(p, e3, p);
    accl2 += __log2f(p);
}

// ===========================================================================
__global__ void __launch_bounds__(TPB, 6) fused_kernel(
    const float* __restrict__ refined,   // [B,F,N,3]
    const float* __restrict__ gt,        // [B,F,N,3]
    const int*   __restrict__ visp,      // [B,F,N]
    const float* __restrict__ proj,      // [V,B,3,4]
    const float* __restrict__ tracks,    // [V,B,F,N,2]
    const float* __restrict__ corr,      // [V,V,B,N,N]
    float* __restrict__ out, int out_size)
{
    const int tid = threadIdx.x;
    __shared__ float sred[8];
    __shared__ double sredd[8];
    __shared__ bool s_last;

    if (blockIdx.x < NB_REC) {
        // ---------------- reconstruction loss partials ----------------
        const int rb = blockIdx.x;
        float ssum = 0.0f, scnt = 0.0f;
        float mn0 = 1e30f, mn1 = 1e30f, mn2 = 1e30f;
        float mx0 = -1e30f, mx1 = -1e30f, mx2 = -1e30f;
        const int p0 = rb * 4096;
#pragma unroll 4
        for (int q = 0; q < 16; q++) {
            int p = p0 + tid + q * TPB;
            int vv = visp[p];
            float gx = gt[3 * p + 0], gy = gt[3 * p + 1], gz = gt[3 * p + 2];
            float px = refined[3 * p + 0], py = refined[3 * p + 1], pz = refined[3 * p + 2];
            if (vv > 0) {
                float dx = px - gx, dy = py - gy, dz = pz - gz;
                ssum += dx * dx + dy * dy + dz * dz;
                scnt += 1.0f;
                mn0 = fminf(mn0, gx); mn1 = fminf(mn1, gy); mn2 = fminf(mn2, gz);
                mx0 = fmaxf(mx0, gx); mx1 = fmaxf(mx1, gy); mx2 = fmaxf(mx2, gz);
            }
        }
        float rs = blockSum(ssum, sred);
        float rc = blockSum(scnt, sred);
        float a0 = blockMin(mn0, sred), a1 = blockMin(mn1, sred), a2 = blockMin(mn2, sred);
        float b0 = blockMax(mx0, sred), b1 = blockMax(mx1, sred), b2 = blockMax(mx2, sred);
        if (tid == 0) {
            g_rec_partial[rb][0] = rs; g_rec_partial[rb][1] = rc;
            g_rec_partial[rb][2] = a0; g_rec_partial[rb][3] = a1; g_rec_partial[rb][4] = a2;
            g_rec_partial[rb][5] = b0; g_rec_partial[rb][6] = b1; g_rec_partial[rb][7] = b2;
        }
    } else if (blockIdx.x < NB_REC + NB_IDENT) {
        // ---------------- identity loss: one block per (v,b,f) group ----------------
        // Eigen-ordered fp32 FMA chain + IEEE division (bit-matches reference;
        // do not touch — the loss is heavy-tailed in 1/h2).
        const int gid = blockIdx.x - NB_REC;         // == (v*B + b)*F + f
        const int f = gid & (F_ - 1);
        const int bb = (gid >> 4) & (B_ - 1);
        const int vv = gid >> 6;
        const float2* trk = (const float2*)(tracks + (long long)gid * (N_ * 2));
        __shared__ float P[12];
        __shared__ float s_wh[2];
        if (tid < 12) P[tid] = proj[(vv * B_ + bb) * 12 + tid];

        float tx[4], ty[4];
        float mnx = 1e30f, mny = 1e30f, mxx = -1e30f, mxy = -1e30f;
#pragma unroll
        for (int q = 0; q < 4; q++) {
            int n = tid + q * TPB;
            float2 t2 = trk[n];
            tx[q] = t2.x; ty[q] = t2.y;
            if (fabsf(t2.x) + fabsf(t2.y) > 1e-6f) {
                mnx = fminf(mnx, t2.x); mxx = fmaxf(mxx, t2.x);
                mny = fminf(mny, t2.y); mxy = fmaxf(mxy, t2.y);
            }
        }
        float rmnx = blockMin(mnx, sred), rmxx = blockMax(mxx, sred);
        float rmny = blockMin(mny, sred), rmxy = blockMax(mxy, sred);
        if (tid == 0) {
            bool anyv = (rmnx <= 1e29f) || (rmny <= 1e29f);
            float whx = anyv ? fmaxf(224.0f, __fadd_rn(__fadd_rn(rmxx, -rmnx), 1e-6f)) : 224.0f;
            float why = anyv ? fmaxf(224.0f, __fadd_rn(__fadd_rn(rmxy, -rmny), 1e-6f)) : 224.0f;
            s_wh[0] = whx;
            s_wh[1] = why;
        }
        __syncthreads();
        float whx = s_wh[0], why = s_wh[1];
        const float* pb = refined + ((long long)(bb * F_ + f) * N_) * 3;
        double errs = 0.0;
#pragma unroll
        for (int q = 0; q < 4; q++) {
            int n = tid + q * TPB;
            float X = pb[3 * n + 0], Y = pb[3 * n + 1], Z = pb[3 * n + 2];
            float h0 = __fmaf_rn(P[3], 1.0f, __fmaf_rn(P[2], Z, __fmaf_rn(P[1], Y, __fmul_rn(P[0], X))));
            float h1 = __fmaf_rn(P[7], 1.0f, __fmaf_rn(P[6], Z, __fmaf_rn(P[5], Y, __fmul_rn(P[4], X))));
            float h2 = __fmaf_rn(P[11], 1.0f, __fmaf_rn(P[10], Z, __fmaf_rn(P[9], Y, __fmul_rn(P[8], X))));
            float den = __fadd_rn(h2, 1e-10f);
            float px = __fdiv_rn(h0, den);
            float py = __fdiv_rn(h1, den);
            float ex = __fdiv_rn(__fadd_rn(px, -tx[q]), whx);
            float ey = __fdiv_rn(__fadd_rn(py, -ty[q]), why);
            float e = __fadd_rn(__fmul_rn(ex, ex), __fmul_rn(ey, ey));
            errs += (double)e;
        }
        double tot = blockSumD(errs, sredd);
        if (tid == 0) g_ident_partial[gid] = tot * (1.0 / (double)N_);
    } else {
        // ---------------- attention BCE loss (the 256 MB stream) ----------------
        // bce = s0 + Delta. s0 uniform over ALL elements; Delta on |i-j|<=2 band.
        // Distance-2 L2 prefetch: demand loads hit L2 (~240cyc) while DRAM fills
        // run 2 iterations ahead — the one lever that measurably raised DRAM%.
        const int ab = blockIdx.x - NB_REC - NB_IDENT;
        __shared__ unsigned int visbits[B_][32];     // frame-0 visibility bitmask
        if (tid < B_ * 32) {
            int b = tid >> 5, wi = tid & 31;
            const int* vp = visp + b * (F_ * N_) + wi * 32;  // frame 0
            unsigned int bits = 0;
#pragma unroll
            for (int k = 0; k < 32; k++) bits |= (vp[k] > 0 ? 1u : 0u) << k;
            visbits[b][wi] = bits;
        }
        __syncthreads();

        float acc = 0.0f;

        // ---- band correction: BAND_RPB rows per att block ----
        for (int r = tid; r < BAND_RPB; r += TPB) {
            int row = ab * BAND_RPB + r;
            if (row < N_ROWS) {
                int m = row >> 10;                   // matrix 0..63
                int i = row & 1023;
                int b = m & (B_ - 1);
                unsigned int vi = (visbits[b][i >> 5] >> (i & 31)) & 1u;
                const float* rowp = corr + ((long long)m << 20) + ((long long)i << 10);
                int jlo = (i >= 2) ? i - 2 : 0;
                int jhi = (i <= 1021) ? i + 2 : 1023;
                float d = 0.0f;
#pragma unroll 5
                for (int j = jlo; j <= jhi; j++) {
                    int ad = (i > j) ? (i - j) : (j - i);
                    unsigned int vj = (visbits[b][j >> 5] >> (j & 31)) & 1u;
                    float band = (ad == 0) ? 1.0f : ((ad == 1) ? 0.7f : 0.49f);
                    float g = (vi | vj) ? band : 0.0f;
                    float x = rowp[j];
                    float mx = fmaxf(x, 0.0f);
                    float l = __logf(1.0f + __expf(-fabsf(x)));
                    d += 2.0f * g * (mx + l) - (1.0f + 2.0f * g) * x * g;
                }
                acc += d;
            }
        }

        // ---- uniform streaming pass: 4-way batched loads + distance-2 prefetch ----
        const float4* c4 = (const float4*)corr;
        const int STR = NB_ATT * TPB;
        float accm0 = 0.0f, accl0 = 0.0f;
        float accm1 = 0.0f, accl1 = 0.0f;
        int idx = ab * TPB + tid;

        // prime: prefetch iteration +0 and +1 lines before the loop
        {
            int pf = idx;
            if (pf + 3 * STR < TOT_F4) {
                prefetchL2(c4 + pf);                prefetchL2(c4 + pf + STR);
                prefetchL2(c4 + pf + 2 * STR);      prefetchL2(c4 + pf + 3 * STR);
            }
            pf = idx + 4 * STR;
            if (pf + 3 * STR < TOT_F4) {
                prefetchL2(c4 + pf);                prefetchL2(c4 + pf + STR);
                prefetchL2(c4 + pf + 2 * STR);      prefetchL2(c4 + pf + 3 * STR);
            }
        }
        for (; idx + 3 * STR < TOT_F4; idx += 4 * STR) {
            float4 v0 = __ldcs(c4 + idx);
            float4 v1 = __ldcs(c4 + idx + STR);
            float4 v2 = __ldcs(c4 + idx + 2 * STR);
            float4 v3 = __ldcs(c4 + idx + 3 * STR);
            // prefetch the iteration TWO ahead (distance-2 pipeline)
            int pf = idx + 8 * STR;
            if (pf + 3 * STR < TOT_F4) {
                prefetchL2(c4 + pf);                prefetchL2(c4 + pf + STR);
                prefetchL2(c4 + pf + 2 * STR);      prefetchL2(c4 + pf + 3 * STR);
            }
            bce4(v0, accm0, accl0);
            bce4(v1, accm1, accl1);
            bce4(v2, accm0, accl0);
            bce4(v3, accm1, accl1);
        }
        for (; idx < TOT_F4; idx += STR) {
            float4 v = __ldcs(c4 + idx);
            bce4(v, accm0, accl0);
        }
        acc += (accm0 + accm1) + (accl0 + accl1) * LN2;

        float tot = blockSum(acc, sred);
        if (tid == 0) g_att_partial[ab] = tot;
    }

    // ================= last-block finalize (no second launch) =================
    if (tid == 0) {
        __threadfence();
        unsigned int t = atomicAdd(&g_done, 1u);
        s_last = (t == (unsigned int)(NB_TOTAL - 1));
    }
    __syncthreads();
    if (s_last) {
        __threadfence();
        int lane = tid & 31, w = tid >> 5;
        __shared__ double shd[8];

        double a = 0.0;
        for (int i = tid; i < NB_ATT; i += TPB) a += (double)g_att_partial[i];
        a = warpSumD(a);
        if (lane == 0) shd[w] = a;
        __syncthreads();
        double asum = (tid < 8) ? shd[tid] : 0.0;
        if (w == 0) asum = warpSumD(asum);
        __syncthreads();

        double id = (tid < NB_IDENT) ? g_ident_partial[tid] : 0.0;
        id = warpSumD(id);
        if (lane == 0) shd[w] = id;
        __syncthreads();
        double idsum = (tid < 8) ? shd[tid] : 0.0;
        if (w == 0) idsum = warpSumD(idsum);

        if (tid == 0) {
            float ssum = 0.0f, scnt = 0.0f;
            float mn[3] = {1e30f, 1e30f, 1e30f};
            float mx[3] = {-1e30f, -1e30f, -1e30f};
            for (int r = 0; r < NB_REC; r++) {
                ssum += g_rec_partial[r][0];
                scnt += g_rec_partial[r][1];
                for (int c = 0; c < 3; c++) {
                    mn[c] = fminf(mn[c], g_rec_partial[r][2 + c]);
                    mx[c] = fmaxf(mx[c], g_rec_partial[r][5 + c]);
                }
            }
            float rng = fmaxf(fmaxf(mx[0] - mn[0], mx[1] - mn[1]), mx[2] - mn[2]);
            float scale = rng + 1e-6f;
            float num = scnt * 3.0f;
            if (!(num > 0.0f)) scale = 1.0f;
            float rec = (ssum / fmaxf(num, 1.0f)) / (scale * scale);

            float ident = (float)(idsum / (double)NB_IDENT);
            float att = (float)(asum / (64.0 * 1048576.0));
            float total = rec + 1.0f * ident + 0.5f * att;
            if (out_size >= 4) {
                out[0] = total; out[1] = rec; out[2] = ident; out[3] = att;
            } else if (out_size >= 1) {
                out[0] = total;
            }
            g_done = 0;   // reset for next (graph-replayed) launch
        }
    }
}

// ===========================================================================
extern "C" void kernel_launch(void* const* d_in, const int* in_sizes, int n_in,
                              void* d_out, int out_size) {
    const float* refined = (const float*)d_in[0];
    const float* gt      = (const float*)d_in[1];
    const int*   visp    = (const int*)  d_in[2];
    const float* proj    = (const float*)d_in[3];
    const float* tracks  = (const float*)d_in[4];
    const float* corr    = (const float*)d_in[5];
    (void)in_sizes; (void)n_in;

    fused_kernel<<<NB_TOTAL, TPB>>>(refined, gt, visp, proj, tracks, corr,
                                    (float*)d_out, out_size);
}